// round 3
// baseline (speedup 1.0000x reference)
#include <cuda_runtime.h>
#include <cuda_bf16.h>

// Problem constants
#define N_   2
#define C_   128
#define D_   48          // input spatial
#define P_   49          // blurred spatial (pad (3,2) + 5-tap valid)
#define OC_  256
#define O_   24          // output spatial

#define BC_  (N_ * C_)   // 256 folded batch*channel

// Scratch (static __device__ arrays — no allocation)
__device__ float g_t1[BC_ * D_ * D_ * P_];   // blur along x: [bc][z48][y48][x49]
__device__ float g_t2[BC_ * D_ * P_ * P_];   // blur along y: [bc][z48][y49][x49]
__device__ float g_xf[BC_ * P_ * P_ * P_];   // blur along z: [bc][z49][y49][x49]

// 5-tap kernel normalized per axis: [1,3,3,3,1]/11 (outer product == k3/1331)
__device__ __forceinline__ float ktap(int e) {
    const float kn[5] = {1.f/11.f, 3.f/11.f, 3.f/11.f, 3.f/11.f, 1.f/11.f};
    return kn[e];
}

// -------- Blur pass X: x[bc][z][y][x48] -> t1[bc][z][y][x49] --------
__global__ void blurX(const float* __restrict__ x) {
    int idx = blockIdx.x * 256 + threadIdx.x;
    const int total = BC_ * D_ * D_ * P_;
    if (idx >= total) return;
    int xo = idx % P_;
    int r  = idx / P_;
    int y  = r % D_;
    int r2 = r / D_;            // bc*48 + z
    const float* row = x + ((long)r2 * D_ + y) * D_;
    float s = 0.f;
    #pragma unroll
    for (int e = 0; e < 5; e++) {
        int xi = xo + e - 3;
        if (xi >= 0 && xi < D_) s += ktap(e) * row[xi];
    }
    g_t1[idx] = s;
}

// -------- Blur pass Y: t1[bc][z][y48][x49] -> t2[bc][z][y49][x49] --------
__global__ void blurY() {
    int idx = blockIdx.x * 256 + threadIdx.x;
    const int total = BC_ * D_ * P_ * P_;
    if (idx >= total) return;
    int xx = idx % P_;
    int r  = idx / P_;
    int yo = r % P_;
    int r2 = r / P_;            // bc*48 + z
    float s = 0.f;
    #pragma unroll
    for (int e = 0; e < 5; e++) {
        int yi = yo + e - 3;
        if (yi >= 0 && yi < D_)
            s += ktap(e) * g_t1[((long)r2 * D_ + yi) * P_ + xx];
    }
    g_t2[idx] = s;
}

// -------- Blur pass Z: t2[bc][z48][y49][x49] -> xf[bc][z49][y49][x49] --------
__global__ void blurZ() {
    int idx = blockIdx.x * 256 + threadIdx.x;
    const int total = BC_ * P_ * P_ * P_;
    if (idx >= total) return;
    int xx = idx % P_;
    int r  = idx / P_;
    int yy = r % P_;
    int r2 = r / P_;            // bc*49 + zo
    int zo = r2 % P_;
    int bc = r2 / P_;
    float s = 0.f;
    #pragma unroll
    for (int e = 0; e < 5; e++) {
        int zi = zo + e - 3;
        if (zi >= 0 && zi < D_)
            s += ktap(e) * g_t2[(((long)bc * D_ + zi) * P_ + yy) * P_ + xx];
    }
    g_xf[idx] = s;
}

// -------- Conv 3x3x3 stride 2 over xf, 128 -> 256 channels, + bias --------
// Block: 192 threads. 32 output channels/block, spatial tile 24(x) x 2(y) x 2(z).
// Thread owns 4 oc x 4 x-outputs (16 accumulators). Per (c,dz,dy): 9 input LDS
// reused across the stride-2 x footprint; weights via broadcast LDS.
__global__ __launch_bounds__(192) void conv3(const float* __restrict__ w,
                                             const float* __restrict__ bias,
                                             float* __restrict__ out) {
    __shared__ float s_in[5 * 5 * 49];   // 1225
    __shared__ float s_w[27 * 32];       // 864 (layout [tap][oc_local])

    int tid = threadIdx.x;
    int ocg = blockIdx.x;                // 0..7  (32 oc each)
    int tyz = blockIdx.y;                // 0..143
    int n   = blockIdx.z;                // 0..1
    int ty = tyz % 12, tz = tyz / 12;
    int oy0 = ty * 2, oz0 = tz * 2;

    int oc_slot = tid / 24;              // 0..7
    int sp      = tid % 24;
    int x_slot  = sp % 6;                // 0..5
    int yzs     = sp / 6;                // 0..3
    int ly = yzs & 1, lz = yzs >> 1;
    int ox0 = x_slot * 4;

    float acc[4][4];
    #pragma unroll
    for (int j = 0; j < 4; j++)
        #pragma unroll
        for (int i = 0; i < 4; i++) acc[j][i] = 0.f;

    const int iz0 = oz0 * 2, iy0 = oy0 * 2;

    for (int c = 0; c < C_; c++) {
        // ---- load input tile 5 x 5 x 49 ----
        const float* src = g_xf + (((long)(n * C_ + c) * P_ + iz0) * P_ + iy0) * P_;
        #pragma unroll 4
        for (int i = tid; i < 1225; i += 192) {
            int xx = i % 49; int r = i / 49; int yy = r % 5; int zz = r / 5;
            s_in[i] = src[(zz * P_ + yy) * P_ + xx];
        }
        // ---- load 32 oc x 27 weights, transposed to [tap][oc] ----
        const float* wsrc = w + ((long)(ocg * 32) * C_ + c) * 27;
        #pragma unroll 5
        for (int i = tid; i < 864; i += 192) {
            int ocl = i / 27; int tap = i % 27;
            s_w[tap * 32 + ocl] = wsrc[(long)ocl * C_ * 27 + tap];
        }
        __syncthreads();

        #pragma unroll
        for (int dz = 0; dz < 3; dz++) {
            #pragma unroll
            for (int dy = 0; dy < 3; dy++) {
                float xv[9];
                const float* p = &s_in[((lz * 2 + dz) * 5 + (ly * 2 + dy)) * 49 + ox0 * 2];
                #pragma unroll
                for (int k = 0; k < 9; k++) xv[k] = p[k];
                #pragma unroll
                for (int dx = 0; dx < 3; dx++) {
                    int tap = (dz * 3 + dy) * 3 + dx;
                    #pragma unroll
                    for (int j = 0; j < 4; j++) {
                        float wv = s_w[tap * 32 + oc_slot * 4 + j];
                        #pragma unroll
                        for (int i = 0; i < 4; i++)
                            acc[j][i] += xv[2 * i + dx] * wv;
                    }
                }
            }
        }
        __syncthreads();
    }

    // ---- epilogue: + bias, store ----
    int oz = oz0 + lz, oy = oy0 + ly;
    #pragma unroll
    for (int j = 0; j < 4; j++) {
        int oc = ocg * 32 + oc_slot * 4 + j;
        float b = bias[oc];
        long base = (((long)n * OC_ + oc) * O_ + oz) * (O_ * O_) + (long)oy * O_;
        #pragma unroll
        for (int i = 0; i < 4; i++)
            out[base + ox0 + i] = acc[j][i] + b;
    }
}

extern "C" void kernel_launch(void* const* d_in, const int* in_sizes, int n_in,
                              void* d_out, int out_size) {
    const float* x    = (const float*)d_in[0];   // (2,128,48,48,48)
    const float* wgt  = (const float*)d_in[1];   // (256,128,3,3,3)
    const float* bias = (const float*)d_in[2];   // (256,)
    float* out = (float*)d_out;                  // (2,256,24,24,24)

    {
        const int total = BC_ * D_ * D_ * P_;
        blurX<<<(total + 255) / 256, 256>>>(x);
    }
    {
        const int total = BC_ * D_ * P_ * P_;
        blurY<<<(total + 255) / 256, 256>>>();
    }
    {
        const int total = BC_ * P_ * P_ * P_;
        blurZ<<<(total + 255) / 256, 256>>>();
    }
    {
        dim3 grid(8, 144, 2);
        conv3<<<grid, 192>>>(wgt, bias, out);
    }
}

// round 5
// speedup vs baseline: 5.4579x; 5.4579x over previous
#include <cuda_runtime.h>
#include <cuda_bf16.h>
#include <cstdint>

// ---------------- problem constants ----------------
#define NN 2
#define CC 128
#define DD 48
#define PP 49
#define OCN 256
#define OO 24
#define NS   (NN*OO*OO*OO)      // 27648 spatial outputs
#define STILES (NS/128)         // 216

// ---------------- scratch (static, no allocation) ----------------
__device__ __align__(16) float g_t1[(size_t)NN*DD*DD*PP*CC];          // [n][z48][y48][x49][c]
__device__ __align__(16) float g_t2[(size_t)NN*DD*PP*PP*CC];          // [n][z48][y49][x49][c]
__device__ __align__(128) __nv_bfloat16 g_xh[(size_t)NN*PP*PP*PP*CC]; // blurred, bf16 hi
__device__ __align__(128) __nv_bfloat16 g_xl[(size_t)NN*PP*PP*PP*CC]; // blurred, bf16 lo
__device__ __align__(128) __nv_bfloat16 g_wh[27*OCN*CC];              // [tap][oc][c] hi
__device__ __align__(128) __nv_bfloat16 g_wl[27*OCN*CC];              // [tap][oc][c] lo

// ---------------- PTX helpers (portable: sm_80+ features only) ----------------
__device__ __forceinline__ uint32_t smem_u32(const void* p) {
    uint32_t a;
    asm("{ .reg .u64 t; cvta.to.shared.u64 t, %1; cvt.u32.u64 %0, t; }" : "=r"(a) : "l"(p));
    return a;
}
__device__ __forceinline__ void cp_async16(uint32_t saddr, const void* gaddr) {
    asm volatile("cp.async.ca.shared.global [%0], [%1], 16;" :: "r"(saddr), "l"(gaddr) : "memory");
}
__device__ __forceinline__ void cp_commit() { asm volatile("cp.async.commit_group;" ::: "memory"); }
__device__ __forceinline__ void cp_wait_all() { asm volatile("cp.async.wait_group 0;" ::: "memory"); }

__device__ __forceinline__ void ldsm_x4(uint32_t* r, uint32_t addr) {
    asm volatile("ldmatrix.sync.aligned.m8n8.x4.shared.b16 {%0,%1,%2,%3}, [%4];"
        : "=r"(r[0]), "=r"(r[1]), "=r"(r[2]), "=r"(r[3]) : "r"(addr));
}
__device__ __forceinline__ void mma16816(float* d, const uint32_t* a, const uint32_t* b) {
    asm volatile("mma.sync.aligned.m16n8k16.row.col.f32.bf16.bf16.f32 "
        "{%0,%1,%2,%3}, {%4,%5,%6,%7}, {%8,%9}, {%0,%1,%2,%3};"
        : "+f"(d[0]), "+f"(d[1]), "+f"(d[2]), "+f"(d[3])
        : "r"(a[0]), "r"(a[1]), "r"(a[2]), "r"(a[3]), "r"(b[0]), "r"(b[1]));
}

// SW128 swizzled byte address of the 16B chunk (row, kb) in a 128rowx128B tile
__device__ __forceinline__ uint32_t sw_addr(uint32_t base, int row, int kb) {
    return base + row * 128 + ((kb ^ (row & 7)) * 16);
}

// ---------------- weight split: w[oc][c][tap] fp32 -> g_wh/g_wl [tap][oc][c] bf16 ----------------
__global__ void wprep(const float* __restrict__ w) {
    int idx = blockIdx.x * 256 + threadIdx.x;
    if (idx >= OCN * CC * 27) return;
    int oc = idx / (CC * 27);
    int r = idx % (CC * 27);
    int c = r / 27, tap = r % 27;
    float v = w[idx];
    __nv_bfloat16 h = __float2bfloat16(v);
    __nv_bfloat16 l = __float2bfloat16(v - __bfloat162float(h));
    int o = (tap * OCN + oc) * CC + c;
    g_wh[o] = h; g_wl[o] = l;
}

// ---------------- blur X + transpose to channel-last ----------------
// x[n][c][z][y][x48] -> t1[n][z][y][x49][c]
__global__ __launch_bounds__(128) void blurX(const float* __restrict__ x) {
    __shared__ float s[128 * 49];   // [c][x] rows padded to 49 (conflict-free)
    int bx = blockIdx.x;            // z*48 + y
    int n = blockIdx.y;
    int z = bx / 48, y = bx % 48;
    int tid = threadIdx.x;
    const float* base = x + (size_t)n * CC * 110592 + (size_t)(z * 48 + y) * 48;
    for (int i = tid; i < 128 * 12; i += 128) {
        int c = i / 12, v = i % 12;
        float4 d = *(const float4*)(base + (size_t)c * 110592 + v * 4);
        float* sr = s + c * 49 + v * 4;
        sr[0] = d.x; sr[1] = d.y; sr[2] = d.z; sr[3] = d.w;
    }
    __syncthreads();
    const float k0 = 1.f / 11.f, k1 = 3.f / 11.f;
    float* dst = g_t1 + ((size_t)((n * 48 + z) * 48 + y)) * 49 * 128;
    const float* sc = s + tid * 49;
    for (int xo = 0; xo < 49; xo++) {
        float v = 0.f;
        #pragma unroll
        for (int e = 0; e < 5; e++) {
            int xi = xo + e - 3;
            float k = (e == 0 || e == 4) ? k0 : k1;
            if (xi >= 0 && xi < 48) v += k * sc[xi];
        }
        dst[xo * 128 + tid] = v;
    }
}

// ---------------- blur Y: t1[nz][y48][xc] -> t2[nz][y49][xc], xc = x49*c128 = 6272 ----------------
__global__ void blurY() {
    int idx = blockIdx.x * 256 + threadIdx.x;
    const int total = NN * 48 * 49 * 6272;
    if (idx >= total) return;
    int xc = idx % 6272;
    int t = idx / 6272;
    int yo = t % 49;
    int nz = t / 49;
    const float k0 = 1.f / 11.f, k1 = 3.f / 11.f;
    const float* bp = g_t1 + (size_t)nz * 48 * 6272 + xc;
    float v = 0.f;
    #pragma unroll
    for (int e = 0; e < 5; e++) {
        int yi = yo + e - 3;
        float k = (e == 0 || e == 4) ? k0 : k1;
        if (yi >= 0 && yi < 48) v += k * bp[(size_t)yi * 6272];
    }
    g_t2[idx] = v;
}

// ---------------- blur Z + bf16 hi/lo split: t2 -> g_xh/g_xl [n][z49][y49][x49][c] ----------------
__global__ void blurZ() {
    int idx = blockIdx.x * 256 + threadIdx.x;
    const int total = NN * 49 * 307328;   // 307328 = 49*49*128
    if (idx >= total) return;
    int w = idx % 307328;
    int t = idx / 307328;
    int zo = t % 49;
    int n = t / 49;
    const float k0 = 1.f / 11.f, k1 = 3.f / 11.f;
    const float* bp = g_t2 + (size_t)n * 48 * 307328 + w;
    float v = 0.f;
    #pragma unroll
    for (int e = 0; e < 5; e++) {
        int zi = zo + e - 3;
        float k = (e == 0 || e == 4) ? k0 : k1;
        if (zi >= 0 && zi < 48) v += k * bp[(size_t)zi * 307328];
    }
    __nv_bfloat16 h = __float2bfloat16(v);
    __nv_bfloat16 l = __float2bfloat16(v - __bfloat162float(h));
    g_xh[idx] = h; g_xl[idx] = l;
}

// ---------------- GEMM via mma.sync bf16 (HMMA.16816), 3-term split ----------------
// CTA: 128 oc x 128 spatial. 8 warps: warp_m=wid%4 (32 rows), warp_n=wid/4 (64 cols).
// 54 stages = 27 taps x 2 channel-halves (K=64 each). smem: 2 bufs x 4 tiles
// (Ah,Al,Bh,Bl) x 16KB, SW128-swizzled rows of 128B (64 bf16 channels).
__global__ __launch_bounds__(256, 1) void gemm_k(const float* __restrict__ bias,
                                                 float* __restrict__ out) {
    extern __shared__ char smem[];
    uint32_t sb = smem_u32(smem);
    int tid = threadIdx.x, wid = tid >> 5, lane = tid & 31;
    int stile = blockIdx.x, ocg = blockIdx.y;
    int wm = (wid & 3) * 32;      // M (oc) offset in CTA tile
    int wn = (wid >> 2) * 64;     // N (spatial) offset

    // issue cp.async for one stage (tap, half) into buffer b
    auto load_stage = [&](int st, int b) {
        int tap = st >> 1, half = st & 1;
        int dz = tap / 9, dy = (tap / 3) % 3, dx = tap % 3;
        uint32_t bufbase = sb + b * 65536;
        #pragma unroll
        for (int it = 0; it < 16; it++) {
            int i = tid + it * 256;
            int t = i >> 10;            // tile id: 0=Ah 1=Al 2=Bh 3=Bl
            int row = (i >> 3) & 127;
            int v = i & 7;
            const void* g;
            if (t < 2) {
                const __nv_bfloat16* wsrc = (t == 0) ? g_wh : g_wl;
                g = (const void*)((const uint4*)(wsrc + ((tap * OCN + ocg * 128 + row) * CC + half * 64)) + v);
            } else {
                int s = stile * 128 + row;
                int n = s / 13824; int r = s % 13824;
                int oz = r / 576, r2 = r % 576, oy = r2 / 24, ox = r2 % 24;
                size_t off = ((size_t)((n * 49 + 2 * oz + dz) * 49 + (2 * oy + dy)) * 49
                              + (2 * ox + dx)) * 128 + half * 64;
                const __nv_bfloat16* xs = (t == 2) ? g_xh : g_xl;
                g = (const void*)((const uint4*)(xs + off) + v);
            }
            cp_async16(bufbase + t * 16384 + (uint32_t)(row * 128 + ((v ^ (row & 7)) * 16)), g);
        }
        cp_commit();
    };

    float acc[2][8][4];
    #pragma unroll
    for (int i = 0; i < 2; i++)
        #pragma unroll
        for (int j = 0; j < 8; j++)
            #pragma unroll
            for (int q = 0; q < 4; q++) acc[i][j][q] = 0.f;

    load_stage(0, 0);
    cp_wait_all();
    __syncthreads();

    for (int st = 0; st < 54; st++) {
        int b = st & 1;
        if (st + 1 < 54) load_stage(st + 1, b ^ 1);

        uint32_t bufbase = sb + b * 65536;
        uint32_t tAh = bufbase, tAl = bufbase + 16384;
        uint32_t tBh = bufbase + 32768, tBl = bufbase + 49152;

        #pragma unroll
        for (int ks = 0; ks < 4; ks++) {
            // A fragments: 2 m16 tiles, hi and lo
            uint32_t ah[2][4], al[2][4];
            int arow = wm + (lane & 15);
            int akb = ks * 2 + (lane >> 4);
            #pragma unroll
            for (int i = 0; i < 2; i++) {
                ldsm_x4(ah[i], sw_addr(tAh, arow + i * 16, akb));
                ldsm_x4(al[i], sw_addr(tAl, arow + i * 16, akb));
            }
            int brow0 = wn + (lane & 7) + ((lane >> 4) << 3);
            int bkb = ks * 2 + ((lane >> 3) & 1);
            #pragma unroll
            for (int j4 = 0; j4 < 4; j4++) {
                uint32_t bh[4], bl[4];
                ldsm_x4(bh, sw_addr(tBh, brow0 + j4 * 16, bkb));
                ldsm_x4(bl, sw_addr(tBl, brow0 + j4 * 16, bkb));
                #pragma unroll
                for (int i = 0; i < 2; i++) {
                    mma16816(acc[i][2 * j4],     ah[i], bh);      // Ah*Bh (n-lo)
                    mma16816(acc[i][2 * j4 + 1], ah[i], bh + 2);  //        (n-hi)
                    mma16816(acc[i][2 * j4],     ah[i], bl);      // Ah*Bl
                    mma16816(acc[i][2 * j4 + 1], ah[i], bl + 2);
                    mma16816(acc[i][2 * j4],     al[i], bh);      // Al*Bh
                    mma16816(acc[i][2 * j4 + 1], al[i], bh + 2);
                }
            }
        }
        cp_wait_all();
        __syncthreads();
    }

    // ---- epilogue: + bias, direct stores (pairs of consecutive spatial) ----
    #pragma unroll
    for (int i = 0; i < 2; i++) {
        int ocb = ocg * 128 + wm + i * 16 + (lane >> 2);
        float bv0 = bias[ocb], bv1 = bias[ocb + 8];
        #pragma unroll
        for (int j = 0; j < 8; j++) {
            int col = wn + j * 8 + (lane & 3) * 2;
            int s = stile * 128 + col;
            int nb = s / 13824, r2 = s % 13824;
            float2 v0 = make_float2(acc[i][j][0] + bv0, acc[i][j][1] + bv0);
            float2 v1 = make_float2(acc[i][j][2] + bv1, acc[i][j][3] + bv1);
            *(float2*)(out + ((size_t)(nb * OCN + ocb) * 13824 + r2)) = v0;
            *(float2*)(out + ((size_t)(nb * OCN + ocb + 8) * 13824 + r2)) = v1;
        }
    }
}

// ---------------- launch ----------------
extern "C" void kernel_launch(void* const* d_in, const int* in_sizes, int n_in,
                              void* d_out, int out_size) {
    const float* x    = (const float*)d_in[0];   // (2,128,48,48,48)
    const float* wgt  = (const float*)d_in[1];   // (256,128,3,3,3)
    const float* bias = (const float*)d_in[2];   // (256,)
    float* out = (float*)d_out;                  // (2,256,24,24,24)

    {
        int total = OCN * CC * 27;
        wprep<<<(total + 255) / 256, 256>>>(wgt);
    }
    {
        dim3 grid(48 * 48, NN);
        blurX<<<grid, 128>>>(x);
    }
    {
        int total = NN * 48 * 49 * 6272;
        blurY<<<(total + 255) / 256, 256>>>();
    }
    {
        int total = NN * 49 * 307328;
        blurZ<<<(total + 255) / 256, 256>>>();
    }
    {
        static int smem_set = 0;
        const int smem_bytes = 2 * 65536;   // 131072
        if (!smem_set) {
            cudaFuncSetAttribute(gemm_k, cudaFuncAttributeMaxDynamicSharedMemorySize, smem_bytes);
            smem_set = 1;
        }
        dim3 grid(STILES, 2);
        gemm_k<<<grid, 256, smem_bytes>>>(bias, out);
    }
}

// round 6
// speedup vs baseline: 6.2214x; 1.1399x over previous
#include <cuda_runtime.h>
#include <cuda_bf16.h>
#include <cstdint>

// ---------------- problem constants ----------------
#define NN 2
#define CC 128
#define DD 48
#define PP 49
#define OCN 256
#define OO 24
#define NS   (NN*OO*OO*OO)      // 27648 spatial outputs
#define STILES (NS/128)         // 216

// ---------------- scratch (static, no allocation) ----------------
__device__ __align__(16) float g_t1[(size_t)NN*DD*DD*PP*CC];          // [n][z48][y48][x49][c]
__device__ __align__(16) float g_t2[(size_t)NN*DD*PP*PP*CC];          // [n][z48][y49][x49][c]
__device__ __align__(128) __nv_bfloat16 g_xh[(size_t)NN*PP*PP*PP*CC]; // blurred, bf16 hi
__device__ __align__(128) __nv_bfloat16 g_xl[(size_t)NN*PP*PP*PP*CC]; // blurred, bf16 lo
__device__ __align__(128) __nv_bfloat16 g_wh[27*OCN*CC];              // [tap][oc][c] hi
__device__ __align__(128) __nv_bfloat16 g_wl[27*OCN*CC];              // [tap][oc][c] lo

// ---------------- PTX helpers (portable: sm_80+ features only) ----------------
__device__ __forceinline__ uint32_t smem_u32(const void* p) {
    uint32_t a;
    asm("{ .reg .u64 t; cvta.to.shared.u64 t, %1; cvt.u32.u64 %0, t; }" : "=r"(a) : "l"(p));
    return a;
}
__device__ __forceinline__ void cp_async16(uint32_t saddr, const void* gaddr) {
    asm volatile("cp.async.ca.shared.global [%0], [%1], 16;" :: "r"(saddr), "l"(gaddr) : "memory");
}
__device__ __forceinline__ void cp_commit() { asm volatile("cp.async.commit_group;" ::: "memory"); }

__device__ __forceinline__ void ldsm_x4(uint32_t* r, uint32_t addr) {
    asm volatile("ldmatrix.sync.aligned.m8n8.x4.shared.b16 {%0,%1,%2,%3}, [%4];"
        : "=r"(r[0]), "=r"(r[1]), "=r"(r[2]), "=r"(r[3]) : "r"(addr));
}
__device__ __forceinline__ void mma16816(float* d, const uint32_t* a, const uint32_t* b) {
    asm volatile("mma.sync.aligned.m16n8k16.row.col.f32.bf16.bf16.f32 "
        "{%0,%1,%2,%3}, {%4,%5,%6,%7}, {%8,%9}, {%0,%1,%2,%3};"
        : "+f"(d[0]), "+f"(d[1]), "+f"(d[2]), "+f"(d[3])
        : "r"(a[0]), "r"(a[1]), "r"(a[2]), "r"(a[3]), "r"(b[0]), "r"(b[1]));
}

// SW128 swizzled byte address of the 16B chunk (row, kb) in a 128rowx128B tile
__device__ __forceinline__ uint32_t sw_addr(uint32_t base, int row, int kb) {
    return base + row * 128 + ((kb ^ (row & 7)) * 16);
}

// ---------------- weight split: w[oc][c][tap] fp32 -> g_wh/g_wl [tap][oc][c] bf16 ----------------
__global__ void wprep(const float* __restrict__ w) {
    int idx = blockIdx.x * 256 + threadIdx.x;
    if (idx >= OCN * CC * 27) return;
    int oc = idx / (CC * 27);
    int r = idx % (CC * 27);
    int c = r / 27, tap = r % 27;
    float v = w[idx];
    __nv_bfloat16 h = __float2bfloat16(v);
    __nv_bfloat16 l = __float2bfloat16(v - __bfloat162float(h));
    int o = (tap * OCN + oc) * CC + c;
    g_wh[o] = h; g_wl[o] = l;
}

// ---------------- blur X + transpose to channel-last ----------------
// x[n][c][z][y][x48] -> t1[n][z][y][x49][c]
__global__ __launch_bounds__(128) void blurX(const float* __restrict__ x) {
    __shared__ float s[128 * 49];   // [c][x] rows padded to 49 (conflict-free)
    int bx = blockIdx.x;            // z*48 + y
    int n = blockIdx.y;
    int z = bx / 48, y = bx % 48;
    int tid = threadIdx.x;
    const float* base = x + (size_t)n * CC * 110592 + (size_t)(z * 48 + y) * 48;
    for (int i = tid; i < 128 * 12; i += 128) {
        int c = i / 12, v = i % 12;
        float4 d = *(const float4*)(base + (size_t)c * 110592 + v * 4);
        float* sr = s + c * 49 + v * 4;
        sr[0] = d.x; sr[1] = d.y; sr[2] = d.z; sr[3] = d.w;
    }
    __syncthreads();
    const float k0 = 1.f / 11.f, k1 = 3.f / 11.f;
    float* dst = g_t1 + ((size_t)((n * 48 + z) * 48 + y)) * 49 * 128;
    const float* sc = s + tid * 49;
    for (int xo = 0; xo < 49; xo++) {
        float v = 0.f;
        #pragma unroll
        for (int e = 0; e < 5; e++) {
            int xi = xo + e - 3;
            float k = (e == 0 || e == 4) ? k0 : k1;
            if (xi >= 0 && xi < 48) v += k * sc[xi];
        }
        dst[xo * 128 + tid] = v;
    }
}

// ---------------- blur Y (float4): t1[nz][y48][xc4] -> t2[nz][y49][xc4], xc4 = 6272/4 = 1568 ----------------
__global__ __launch_bounds__(256) void blurY() {
    int idx = blockIdx.x * 256 + threadIdx.x;
    const int total = NN * 48 * 49 * 1568;
    if (idx >= total) return;
    int xc = idx % 1568;
    int t = idx / 1568;
    int yo = t % 49;
    int nz = t / 49;
    const float k0 = 1.f / 11.f, k1 = 3.f / 11.f;
    const float4* bp = (const float4*)g_t1 + (size_t)nz * 48 * 1568 + xc;
    float4 a = make_float4(0.f, 0.f, 0.f, 0.f);
    #pragma unroll
    for (int e = 0; e < 5; e++) {
        int yi = yo + e - 3;
        float k = (e == 0 || e == 4) ? k0 : k1;
        if (yi >= 0 && yi < 48) {
            float4 d = bp[(size_t)yi * 1568];
            a.x += k * d.x; a.y += k * d.y; a.z += k * d.z; a.w += k * d.w;
        }
    }
    ((float4*)g_t2)[idx] = a;
}

// ---------------- blur Z (float4) + bf16 hi/lo split -> g_xh/g_xl [n][z49][y49][x49][c] ----------------
__global__ __launch_bounds__(256) void blurZ() {
    int idx = blockIdx.x * 256 + threadIdx.x;
    const int total = NN * 49 * 76832;      // 76832 = 49*49*128/4
    if (idx >= total) return;
    int w = idx % 76832;
    int t = idx / 76832;
    int zo = t % 49;
    int n = t / 49;
    const float k0 = 1.f / 11.f, k1 = 3.f / 11.f;
    const float4* bp = (const float4*)g_t2 + (size_t)n * 48 * 76832 + w;
    float4 a = make_float4(0.f, 0.f, 0.f, 0.f);
    #pragma unroll
    for (int e = 0; e < 5; e++) {
        int zi = zo + e - 3;
        float k = (e == 0 || e == 4) ? k0 : k1;
        if (zi >= 0 && zi < 48) {
            float4 d = bp[(size_t)zi * 76832];
            a.x += k * d.x; a.y += k * d.y; a.z += k * d.z; a.w += k * d.w;
        }
    }
    float v[4] = {a.x, a.y, a.z, a.w};
    uint32_t hp[2], lp[2];
    #pragma unroll
    for (int q = 0; q < 2; q++) {
        __nv_bfloat16 h0 = __float2bfloat16(v[2*q]);
        __nv_bfloat16 h1 = __float2bfloat16(v[2*q+1]);
        __nv_bfloat16 l0 = __float2bfloat16(v[2*q]   - __bfloat162float(h0));
        __nv_bfloat16 l1 = __float2bfloat16(v[2*q+1] - __bfloat162float(h1));
        hp[q] = (uint32_t)*(uint16_t*)&h0 | ((uint32_t)*(uint16_t*)&h1 << 16);
        lp[q] = (uint32_t)*(uint16_t*)&l0 | ((uint32_t)*(uint16_t*)&l1 << 16);
    }
    ((uint2*)g_xh)[idx] = make_uint2(hp[0], hp[1]);
    ((uint2*)g_xl)[idx] = make_uint2(lp[0], lp[1]);
}

// ---------------- GEMM via mma.sync bf16 (HMMA.16816), 3-term split ----------------
// CTA: 128 oc x 128 spatial. 8 warps: warp_m=wid%4 (32 rows), warp_n=wid/4 (64 cols).
// 54 stages = 27 taps x 2 channel-halves (K=64 each). smem: 3 bufs x 4 tiles
// (Ah,Al,Bh,Bl) x 16KB, SW128-swizzled rows of 128B. cp.async depth-2 pipeline.
__global__ __launch_bounds__(256, 1) void gemm_k(const float* __restrict__ bias,
                                                 float* __restrict__ out) {
    extern __shared__ char smem[];
    __shared__ int s_soff[128];
    uint32_t sb = smem_u32(smem);
    int tid = threadIdx.x, wid = tid >> 5, lane = tid & 31;
    int stile = blockIdx.x, ocg = blockIdx.y;
    int wm = (wid & 3) * 32;      // M (oc) offset in CTA tile
    int wn = (wid >> 2) * 64;     // N (spatial) offset

    // spatial base offsets (elements/128) for this CTA's 128 columns — computed once
    if (tid < 128) {
        int s = stile * 128 + tid;
        int n = s / 13824; int r = s % 13824;
        int oz = r / 576, r2 = r % 576, oy = r2 / 24, ox = r2 % 24;
        s_soff[tid] = ((n * 49 + 2 * oz) * 49 + 2 * oy) * 49 + 2 * ox;
    }
    __syncthreads();

    // issue cp.async for one stage (tap, half) into buffer b
    auto load_stage = [&](int st, int b) {
        int tap = st >> 1, half = st & 1;
        int dz = tap / 9, dy = (tap / 3) % 3, dx = tap % 3;
        int dtap = dz * 2401 + dy * 49 + dx;
        uint32_t bufbase = sb + b * 65536;
        size_t adelta = (size_t)tap * 65536 + half * 128;       // bytes
        size_t bdelta = (size_t)dtap * 256 + half * 128;        // bytes
        #pragma unroll
        for (int it = 0; it < 16; it++) {
            int t = it >> 2;            // tile id: 0=Ah 1=Al 2=Bh 3=Bl
            int i = tid + it * 256;
            int row = (i >> 3) & 127;
            int v = i & 7;
            const char* g;
            if (t < 2) {
                const char* wsrc = (const char*)((t == 0) ? g_wh : g_wl);
                g = wsrc + adelta + (size_t)(ocg * 128 + row) * 256 + v * 16;
            } else {
                const char* xs = (const char*)((t == 2) ? g_xh : g_xl);
                g = xs + bdelta + (size_t)s_soff[row] * 256 + v * 16;
            }
            cp_async16(bufbase + t * 16384 + (uint32_t)(row * 128 + ((v ^ (row & 7)) * 16)), g);
        }
        cp_commit();
    };

    float acc[2][8][4];
    #pragma unroll
    for (int i = 0; i < 2; i++)
        #pragma unroll
        for (int j = 0; j < 8; j++)
            #pragma unroll
            for (int q = 0; q < 4; q++) acc[i][j][q] = 0.f;

    load_stage(0, 0);
    load_stage(1, 1);

    for (int st = 0; st < 54; st++) {
        int b = st % 3;
        if (st >= 52) asm volatile("cp.async.wait_group 0;" ::: "memory");
        else          asm volatile("cp.async.wait_group 1;" ::: "memory");
        __syncthreads();
        if (st + 2 < 54) load_stage(st + 2, (st + 2) % 3);

        uint32_t bufbase = sb + b * 65536;
        uint32_t tAh = bufbase, tAl = bufbase + 16384;
        uint32_t tBh = bufbase + 32768, tBl = bufbase + 49152;

        #pragma unroll
        for (int ks = 0; ks < 4; ks++) {
            uint32_t ah[2][4], al[2][4];
            int arow = wm + (lane & 15);
            int akb = ks * 2 + (lane >> 4);
            #pragma unroll
            for (int i = 0; i < 2; i++) {
                ldsm_x4(ah[i], sw_addr(tAh, arow + i * 16, akb));
                ldsm_x4(al[i], sw_addr(tAl, arow + i * 16, akb));
            }
            int brow0 = wn + (lane & 7) + ((lane >> 4) << 3);
            int bkb = ks * 2 + ((lane >> 3) & 1);
            #pragma unroll
            for (int j4 = 0; j4 < 4; j4++) {
                uint32_t bh[4], bl[4];
                ldsm_x4(bh, sw_addr(tBh, brow0 + j4 * 16, bkb));
                ldsm_x4(bl, sw_addr(tBl, brow0 + j4 * 16, bkb));
                #pragma unroll
                for (int i = 0; i < 2; i++) {
                    mma16816(acc[i][2 * j4],     ah[i], bh);      // Ah*Bh (n-lo)
                    mma16816(acc[i][2 * j4 + 1], ah[i], bh + 2);  //        (n-hi)
                    mma16816(acc[i][2 * j4],     ah[i], bl);      // Ah*Bl
                    mma16816(acc[i][2 * j4 + 1], ah[i], bl + 2);
                    mma16816(acc[i][2 * j4],     al[i], bh);      // Al*Bh
                    mma16816(acc[i][2 * j4 + 1], al[i], bh + 2);
                }
            }
        }
        __syncthreads();
    }

    // ---- epilogue: + bias, direct stores (pairs of consecutive spatial) ----
    #pragma unroll
    for (int i = 0; i < 2; i++) {
        int ocb = ocg * 128 + wm + i * 16 + (lane >> 2);
        float bv0 = bias[ocb], bv1 = bias[ocb + 8];
        #pragma unroll
        for (int j = 0; j < 8; j++) {
            int col = wn + j * 8 + (lane & 3) * 2;
            int s = stile * 128 + col;
            int nb = s / 13824, r2 = s % 13824;
            float2 v0 = make_float2(acc[i][j][0] + bv0, acc[i][j][1] + bv0);
            float2 v1 = make_float2(acc[i][j][2] + bv1, acc[i][j][3] + bv1);
            *(float2*)(out + ((size_t)(nb * OCN + ocb) * 13824 + r2)) = v0;
            *(float2*)(out + ((size_t)(nb * OCN + ocb + 8) * 13824 + r2)) = v1;
        }
    }
}

// ---------------- launch ----------------
extern "C" void kernel_launch(void* const* d_in, const int* in_sizes, int n_in,
                              void* d_out, int out_size) {
    const float* x    = (const float*)d_in[0];   // (2,128,48,48,48)
    const float* wgt  = (const float*)d_in[1];   // (256,128,3,3,3)
    const float* bias = (const float*)d_in[2];   // (256,)
    float* out = (float*)d_out;                  // (2,256,24,24,24)

    {
        int total = OCN * CC * 27;
        wprep<<<(total + 255) / 256, 256>>>(wgt);
    }
    {
        dim3 grid(48 * 48, NN);
        blurX<<<grid, 128>>>(x);
    }
    {
        int total = NN * 48 * 49 * 1568;
        blurY<<<(total + 255) / 256, 256>>>();
    }
    {
        int total = NN * 49 * 76832;
        blurZ<<<(total + 255) / 256, 256>>>();
    }
    {
        static int smem_set = 0;
        const int smem_bytes = 3 * 65536;   // 196608
        if (!smem_set) {
            cudaFuncSetAttribute(gemm_k, cudaFuncAttributeMaxDynamicSharedMemorySize, smem_bytes);
            smem_set = 1;
        }
        dim3 grid(STILES, 2);
        gemm_k<<<grid, 256, smem_bytes>>>(bias, out);
    }
}

// round 8
// speedup vs baseline: 8.3779x; 1.3466x over previous
#include <cuda_runtime.h>
#include <cuda_bf16.h>
#include <cuda_fp16.h>
#include <cstdint>

// ---------------- problem constants ----------------
#define NN 2
#define CC 128
#define DD 48
#define PP 49
#define OCN 256
#define OO 24
#define NS   (NN*OO*OO*OO)      // 27648 spatial outputs
#define STILES (NS/128)         // 216

// ---------------- scratch (static, no allocation) ----------------
__device__ __align__(16) float g_t1[(size_t)NN*DD*DD*PP*CC];      // [n][z48][y48][x49][c]
__device__ __align__(16) float g_t2[(size_t)NN*DD*PP*PP*CC];      // [n][z48][y49][x49][c]
__device__ __align__(128) __half g_xh[(size_t)NN*PP*PP*PP*CC];    // blurred, fp16 hi
__device__ __align__(128) __half g_xl[(size_t)NN*PP*PP*PP*CC];    // blurred, fp16 residual
__device__ __align__(128) __half g_w[27*OCN*CC];                  // [tap][oc][c] fp16

// ---------------- PTX helpers (portable: sm_80+ features only) ----------------
__device__ __forceinline__ uint32_t smem_u32(const void* p) {
    uint32_t a;
    asm("{ .reg .u64 t; cvta.to.shared.u64 t, %1; cvt.u32.u64 %0, t; }" : "=r"(a) : "l"(p));
    return a;
}
__device__ __forceinline__ void cp_async16(uint32_t saddr, const void* gaddr) {
    asm volatile("cp.async.cg.shared.global [%0], [%1], 16;" :: "r"(saddr), "l"(gaddr) : "memory");
}
__device__ __forceinline__ void cp_commit() { asm volatile("cp.async.commit_group;" ::: "memory"); }

__device__ __forceinline__ void ldsm_x4(uint32_t* r, uint32_t addr) {
    asm volatile("ldmatrix.sync.aligned.m8n8.x4.shared.b16 {%0,%1,%2,%3}, [%4];"
        : "=r"(r[0]), "=r"(r[1]), "=r"(r[2]), "=r"(r[3]) : "r"(addr));
}
__device__ __forceinline__ void mma16816(float* d, const uint32_t* a, const uint32_t* b) {
    asm volatile("mma.sync.aligned.m16n8k16.row.col.f32.f16.f16.f32 "
        "{%0,%1,%2,%3}, {%4,%5,%6,%7}, {%8,%9}, {%0,%1,%2,%3};"
        : "+f"(d[0]), "+f"(d[1]), "+f"(d[2]), "+f"(d[3])
        : "r"(a[0]), "r"(a[1]), "r"(a[2]), "r"(a[3]), "r"(b[0]), "r"(b[1]));
}

// SW128 swizzled byte address of the 16B chunk (row, kb) in a 128row x 128B tile
__device__ __forceinline__ uint32_t sw_addr(uint32_t base, int row, int kb) {
    return base + row * 128 + ((kb ^ (row & 7)) * 16);
}

// ---------------- weight prep: w[oc][c][tap] fp32 -> g_w [tap][oc][c] fp16 ----------------
__global__ void wprep(const float* __restrict__ w) {
    int idx = blockIdx.x * 256 + threadIdx.x;
    if (idx >= OCN * CC * 27) return;
    int oc = idx / (CC * 27);
    int r = idx % (CC * 27);
    int c = r / 27, tap = r % 27;
    g_w[(tap * OCN + oc) * CC + c] = __float2half(w[idx]);
}

// ---------------- blur X + transpose to channel-last ----------------
// x[n][c][z][y][x48] -> t1[n][z][y][x49][c]
__global__ __launch_bounds__(128) void blurX(const float* __restrict__ x) {
    __shared__ float s[128 * 49];   // [c][x] rows padded to 49 (conflict-free)
    int bx = blockIdx.x;            // z*48 + y
    int n = blockIdx.y;
    int z = bx / 48, y = bx % 48;
    int tid = threadIdx.x;
    const float* base = x + (size_t)n * CC * 110592 + (size_t)(z * 48 + y) * 48;
    for (int i = tid; i < 128 * 12; i += 128) {
        int c = i / 12, v = i % 12;
        float4 d = *(const float4*)(base + (size_t)c * 110592 + v * 4);
        float* sr = s + c * 49 + v * 4;
        sr[0] = d.x; sr[1] = d.y; sr[2] = d.z; sr[3] = d.w;
    }
    __syncthreads();
    const float k0 = 1.f / 11.f, k1 = 3.f / 11.f;
    float* dst = g_t1 + ((size_t)((n * 48 + z) * 48 + y)) * 49 * 128;
    const float* sc = s + tid * 49;
    for (int xo = 0; xo < 49; xo++) {
        float v = 0.f;
        #pragma unroll
        for (int e = 0; e < 5; e++) {
            int xi = xo + e - 3;
            float k = (e == 0 || e == 4) ? k0 : k1;
            if (xi >= 0 && xi < 48) v += k * sc[xi];
        }
        dst[xo * 128 + tid] = v;
    }
}

// ---------------- blur Y (float4): t1[nz][y48][xc4] -> t2[nz][y49][xc4] ----------------
__global__ __launch_bounds__(256) void blurY() {
    int idx = blockIdx.x * 256 + threadIdx.x;
    const int total = NN * 48 * 49 * 1568;
    if (idx >= total) return;
    int xc = idx % 1568;
    int t = idx / 1568;
    int yo = t % 49;
    int nz = t / 49;
    const float k0 = 1.f / 11.f, k1 = 3.f / 11.f;
    const float4* bp = (const float4*)g_t1 + (size_t)nz * 48 * 1568 + xc;
    float4 a = make_float4(0.f, 0.f, 0.f, 0.f);
    #pragma unroll
    for (int e = 0; e < 5; e++) {
        int yi = yo + e - 3;
        float k = (e == 0 || e == 4) ? k0 : k1;
        if (yi >= 0 && yi < 48) {
            float4 d = bp[(size_t)yi * 1568];
            a.x += k * d.x; a.y += k * d.y; a.z += k * d.z; a.w += k * d.w;
        }
    }
    ((float4*)g_t2)[idx] = a;
}

// ---------------- blur Z (float4) + fp16 hi/lo split -> g_xh/g_xl ----------------
__global__ __launch_bounds__(256) void blurZ() {
    int idx = blockIdx.x * 256 + threadIdx.x;
    const int total = NN * 49 * 76832;      // 76832 = 49*49*128/4
    if (idx >= total) return;
    int w = idx % 76832;
    int t = idx / 76832;
    int zo = t % 49;
    int n = t / 49;
    const float k0 = 1.f / 11.f, k1 = 3.f / 11.f;
    const float4* bp = (const float4*)g_t2 + (size_t)n * 48 * 76832 + w;
    float4 a = make_float4(0.f, 0.f, 0.f, 0.f);
    #pragma unroll
    for (int e = 0; e < 5; e++) {
        int zi = zo + e - 3;
        float k = (e == 0 || e == 4) ? k0 : k1;
        if (zi >= 0 && zi < 48) {
            float4 d = bp[(size_t)zi * 76832];
            a.x += k * d.x; a.y += k * d.y; a.z += k * d.z; a.w += k * d.w;
        }
    }
    float v[4] = {a.x, a.y, a.z, a.w};
    uint32_t hp[2], lp[2];
    #pragma unroll
    for (int q = 0; q < 2; q++) {
        __half h0 = __float2half(v[2*q]);
        __half h1 = __float2half(v[2*q+1]);
        __half l0 = __float2half(v[2*q]   - __half2float(h0));
        __half l1 = __float2half(v[2*q+1] - __half2float(h1));
        hp[q] = (uint32_t)__half_as_ushort(h0) | ((uint32_t)__half_as_ushort(h1) << 16);
        lp[q] = (uint32_t)__half_as_ushort(l0) | ((uint32_t)__half_as_ushort(l1) << 16);
    }
    ((uint2*)g_xh)[idx] = make_uint2(hp[0], hp[1]);
    ((uint2*)g_xl)[idx] = make_uint2(lp[0], lp[1]);
}

// ---------------- GEMM via mma.sync fp16 (HMMA.16816), 2-term split ----------------
// CTA: 128 oc x 128 spatial. 8 warps: 2M x 4N, warp tile 64 x 32.
// 54 stages = 27 taps x 2 channel-halves (K=64). Stage smem = 3 tiles
// (W, Xh, Xl) x 16KB = 48KB; 3 buffers; cp.async depth-2 pipeline, 1 sync/stage.
__global__ __launch_bounds__(256, 1) void gemm_k(const float* __restrict__ bias,
                                                 float* __restrict__ out) {
    extern __shared__ char smem[];
    __shared__ int s_soff[128];
    uint32_t sb = smem_u32(smem);
    int tid = threadIdx.x, wid = tid >> 5, lane = tid & 31;
    int stile = blockIdx.x, ocg = blockIdx.y;
    int wm = (wid & 1) * 64;      // M (oc) offset in CTA tile
    int wn = (wid >> 1) * 32;     // N (spatial) offset

    // spatial base offsets (in 256B units of channel-last layout) — computed once
    if (tid < 128) {
        int s = stile * 128 + tid;
        int n = s / 13824; int r = s % 13824;
        int oz = r / 576, r2 = r % 576, oy = r2 / 24, ox = r2 % 24;
        s_soff[tid] = ((n * 49 + 2 * oz) * 49 + 2 * oy) * 49 + 2 * ox;
    }
    __syncthreads();

    // issue cp.async for one stage (tap, half) into buffer b
    auto load_stage = [&](int st, int b) {
        int tap = st >> 1, half = st & 1;
        int dz = tap / 9, dy = (tap / 3) % 3, dx = tap % 3;
        int dtap = dz * 2401 + dy * 49 + dx;
        uint32_t bufbase = sb + b * 49152;
        size_t adelta = (size_t)tap * 65536 + half * 128;       // bytes into g_w
        size_t bdelta = (size_t)dtap * 256 + half * 128;        // bytes into g_xh/g_xl
        #pragma unroll
        for (int it = 0; it < 12; it++) {
            int t = it >> 2;            // tile id: 0=W 1=Xh 2=Xl
            int i = tid + it * 256;
            int row = (i >> 3) & 127;
            int v = i & 7;
            const char* g;
            if (t == 0) {
                g = (const char*)g_w + adelta + (size_t)(ocg * 128 + row) * 256 + v * 16;
            } else {
                const char* xs = (const char*)((t == 1) ? g_xh : g_xl);
                g = xs + bdelta + (size_t)s_soff[row] * 256 + v * 16;
            }
            cp_async16(bufbase + t * 16384 + (uint32_t)(row * 128 + ((v ^ (row & 7)) * 16)), g);
        }
        cp_commit();
    };

    float acc[4][4][4];
    #pragma unroll
    for (int i = 0; i < 4; i++)
        #pragma unroll
        for (int j = 0; j < 4; j++)
            #pragma unroll
            for (int q = 0; q < 4; q++) acc[i][j][q] = 0.f;

    load_stage(0, 0);
    load_stage(1, 1);

    for (int st = 0; st < 54; st++) {
        int b = st % 3;
        if (st >= 52) asm volatile("cp.async.wait_group 0;" ::: "memory");
        else          asm volatile("cp.async.wait_group 1;" ::: "memory");
        __syncthreads();   // all warps done with stage st-1 -> safe to refill its buffer
        if (st + 2 < 54) load_stage(st + 2, (st + 2) % 3);

        uint32_t bufbase = sb + b * 49152;
        uint32_t tW = bufbase, tXh = bufbase + 16384, tXl = bufbase + 32768;

        #pragma unroll
        for (int ks = 0; ks < 4; ks++) {
            uint32_t aw[4][4];
            int arow = wm + (lane & 15);
            int akb = ks * 2 + (lane >> 4);
            #pragma unroll
            for (int i = 0; i < 4; i++)
                ldsm_x4(aw[i], sw_addr(tW, arow + i * 16, akb));
            int brow0 = wn + (lane & 7) + ((lane >> 4) << 3);
            int bkb = ks * 2 + ((lane >> 3) & 1);
            #pragma unroll
            for (int j2 = 0; j2 < 2; j2++) {
                uint32_t bh[4], bl[4];
                ldsm_x4(bh, sw_addr(tXh, brow0 + j2 * 16, bkb));
                ldsm_x4(bl, sw_addr(tXl, brow0 + j2 * 16, bkb));
                #pragma unroll
                for (int i = 0; i < 4; i++) {
                    mma16816(acc[i][2 * j2],     aw[i], bh);      // W*Xh (n-lo)
                    mma16816(acc[i][2 * j2 + 1], aw[i], bh + 2);  //       (n-hi)
                    mma16816(acc[i][2 * j2],     aw[i], bl);      // W*Xl
                    mma16816(acc[i][2 * j2 + 1], aw[i], bl + 2);
                }
            }
        }
    }

    // ---- epilogue: + bias, direct stores (pairs of consecutive spatial) ----
    #pragma unroll
    for (int i = 0; i < 4; i++) {
        int ocb = ocg * 128 + wm + i * 16 + (lane >> 2);
        float bv0 = bias[ocb], bv1 = bias[ocb + 8];
        #pragma unroll
        for (int j = 0; j < 4; j++) {
            int col = wn + j * 8 + (lane & 3) * 2;
            int s = stile * 128 + col;
            int nb = s / 13824, r2 = s % 13824;
            float2 v0 = make_float2(acc[i][j][0] + bv0, acc[i][j][1] + bv0);
            float2 v1 = make_float2(acc[i][j][2] + bv1, acc[i][j][3] + bv1);
            *(float2*)(out + ((size_t)(nb * OCN + ocb) * 13824 + r2)) = v0;
            *(float2*)(out + ((size_t)(nb * OCN + ocb + 8) * 13824 + r2)) = v1;
        }
    }
}

// ---------------- launch ----------------
extern "C" void kernel_launch(void* const* d_in, const int* in_sizes, int n_in,
                              void* d_out, int out_size) {
    const float* x    = (const float*)d_in[0];   // (2,128,48,48,48)
    const float* wgt  = (const float*)d_in[1];   // (256,128,3,3,3)
    const float* bias = (const float*)d_in[2];   // (256,)
    float* out = (float*)d_out;                  // (2,256,24,24,24)

    {
        int total = OCN * CC * 27;
        wprep<<<(total + 255) / 256, 256>>>(wgt);
    }
    {
        dim3 grid(48 * 48, NN);
        blurX<<<grid, 128>>>(x);
    }
    {
        int total = NN * 48 * 49 * 1568;
        blurY<<<(total + 255) / 256, 256>>>();
    }
    {
        int total = NN * 49 * 76832;
        blurZ<<<(total + 255) / 256, 256>>>();
    }
    {
        static int smem_set = 0;
        const int smem_bytes = 3 * 49152;   // 147456
        if (!smem_set) {
            cudaFuncSetAttribute(gemm_k, cudaFuncAttributeMaxDynamicSharedMemorySize, smem_bytes);
            smem_set = 1;
        }
        dim3 grid(STILES, 2);
        gemm_k<<<grid, 256, smem_bytes>>>(bias, out);
    }
}

// round 10
// speedup vs baseline: 12.5041x; 1.4925x over previous
#include <cuda_runtime.h>
#include <cuda_bf16.h>
#include <cuda_fp16.h>
#include <cstdint>

// ---------------- problem constants ----------------
#define NN 2
#define CC 128
#define DD 48
#define PP 49
#define OCN 256
#define OO 24
#define NS   (NN*OO*OO*OO)      // 27648 spatial outputs
#define STILES (NS/128)         // 216

// ---------------- scratch (static, no allocation) ----------------
__device__ __align__(16) float g_t1[(size_t)NN*DD*DD*PP*CC];      // [n][z48][y48][x49][c]
__device__ __align__(128) __half g_xh[(size_t)NN*PP*PP*PP*CC];    // blurred, fp16
__device__ __align__(128) __half g_w[27*OCN*CC];                  // [tap][oc][c] fp16

// ---------------- PTX helpers (portable: sm_80+ features only) ----------------
__device__ __forceinline__ uint32_t smem_u32(const void* p) {
    uint32_t a;
    asm("{ .reg .u64 t; cvta.to.shared.u64 t, %1; cvt.u32.u64 %0, t; }" : "=r"(a) : "l"(p));
    return a;
}
__device__ __forceinline__ void cp_async16(uint32_t saddr, const void* gaddr) {
    asm volatile("cp.async.cg.shared.global [%0], [%1], 16;" :: "r"(saddr), "l"(gaddr) : "memory");
}
__device__ __forceinline__ void cp_commit() { asm volatile("cp.async.commit_group;" ::: "memory"); }

__device__ __forceinline__ void ldsm_x4(uint32_t* r, uint32_t addr) {
    asm volatile("ldmatrix.sync.aligned.m8n8.x4.shared.b16 {%0,%1,%2,%3}, [%4];"
        : "=r"(r[0]), "=r"(r[1]), "=r"(r[2]), "=r"(r[3]) : "r"(addr));
}
__device__ __forceinline__ void mma16816(float* d, const uint32_t* a, const uint32_t* b) {
    asm volatile("mma.sync.aligned.m16n8k16.row.col.f32.f16.f16.f32 "
        "{%0,%1,%2,%3}, {%4,%5,%6,%7}, {%8,%9}, {%0,%1,%2,%3};"
        : "+f"(d[0]), "+f"(d[1]), "+f"(d[2]), "+f"(d[3])
        : "r"(a[0]), "r"(a[1]), "r"(a[2]), "r"(a[3]), "r"(b[0]), "r"(b[1]));
}

// SW128 swizzled byte address of the 16B chunk (row, kb) in a 128row x 128B tile
__device__ __forceinline__ uint32_t sw_addr(uint32_t base, int row, int kb) {
    return base + row * 128 + ((kb ^ (row & 7)) * 16);
}

// ---------------- weight prep: w[oc][c][tap] fp32 -> g_w [tap][oc][c] fp16 ----------------
__global__ void wprep(const float* __restrict__ w) {
    int idx = blockIdx.x * 256 + threadIdx.x;
    if (idx >= OCN * CC * 27) return;
    int oc = idx / (CC * 27);
    int r = idx % (CC * 27);
    int c = r / 27, tap = r % 27;
    g_w[(tap * OCN + oc) * CC + c] = __float2half(w[idx]);
}

// ---------------- blur X + transpose to channel-last ----------------
// x[n][c][z][y][x48] -> t1[n][z][y][x49][c]
__global__ __launch_bounds__(128) void blurX(const float* __restrict__ x) {
    __shared__ float s[128 * 49];   // [c][x] rows padded to 49 (conflict-free)
    int bx = blockIdx.x;            // z*48 + y
    int n = blockIdx.y;
    int z = bx / 48, y = bx % 48;
    int tid = threadIdx.x;
    const float* base = x + (size_t)n * CC * 110592 + (size_t)(z * 48 + y) * 48;
    for (int i = tid; i < 128 * 12; i += 128) {
        int c = i / 12, v = i % 12;
        float4 d = *(const float4*)(base + (size_t)c * 110592 + v * 4);
        float* sr = s + c * 49 + v * 4;
        sr[0] = d.x; sr[1] = d.y; sr[2] = d.z; sr[3] = d.w;
    }
    __syncthreads();
    const float k0 = 1.f / 11.f, k1 = 3.f / 11.f;
    float* dst = g_t1 + ((size_t)((n * 48 + z) * 48 + y)) * 49 * 128;
    const float* sc = s + tid * 49;
    for (int xo = 0; xo < 49; xo++) {
        float v = 0.f;
        #pragma unroll
        for (int e = 0; e < 5; e++) {
            int xi = xo + e - 3;
            float k = (e == 0 || e == 4) ? k0 : k1;
            if (xi >= 0 && xi < 48) v += k * sc[xi];
        }
        dst[xo * 128 + tid] = v;
    }
}

// ---------------- fused blur Y+Z, fp16 out ----------------
// t1[n][z48][y48][xc] -> g_xh[n][z49][y49][xc], xc = x49*c128/4 = 1568 float4 lanes.
// Thread: fixed (n, yo, xc); streams z with a 5-deep register ring of y-blurred rows.
__global__ __launch_bounds__(256) void blurYZ() {
    int idx = blockIdx.x * 256 + threadIdx.x;
    const int total = NN * PP * 1568;      // (n, yo, xc)
    if (idx >= total) return;
    int xc = idx % 1568;
    int t = idx / 1568;
    int yo = t % PP;
    int n = t / PP;
    const float k0 = 1.f / 11.f, k1 = 3.f / 11.f;

    // valid y taps for this yo
    int yis[5]; float wy[5]; int nty = 0;
    #pragma unroll
    for (int e = 0; e < 5; e++) {
        int yi = yo + e - 3;
        if (yi >= 0 && yi < 48) { yis[nty] = yi; wy[nty] = (e == 0 || e == 4) ? k0 : k1; nty++; }
    }

    const float4* t1b = (const float4*)g_t1 + (size_t)n * 48 * 48 * 1568 + xc;
    uint2* dst = (uint2*)g_xh + ((size_t)n * PP * PP + yo) * 1568 + xc;   // +zo*PP*1568 per slice

    float4 r0, r1, r2, r3, r4;
    r0 = r1 = r2 = r3 = r4 = make_float4(0.f, 0.f, 0.f, 0.f);

    for (int zi = 0; zi < 50; zi++) {
        float4 ty = make_float4(0.f, 0.f, 0.f, 0.f);
        if (zi < 48) {
            for (int q = 0; q < nty; q++) {
                float4 d = t1b[(size_t)(zi * 48 + yis[q]) * 1568];
                float k = wy[q];
                ty.x += k * d.x; ty.y += k * d.y; ty.z += k * d.z; ty.w += k * d.w;
            }
        }
        r0 = r1; r1 = r2; r2 = r3; r3 = r4; r4 = ty;
        int zo = zi - 1;
        if (zo >= 0) {
            // out = k0*ty[zo-3] + k1*(ty[zo-2..zo]) + k0*ty[zo+1]; ring zeros handle bounds
            float4 o;
            o.x = k0 * (r0.x + r4.x) + k1 * (r1.x + r2.x + r3.x);
            o.y = k0 * (r0.y + r4.y) + k1 * (r1.y + r2.y + r3.y);
            o.z = k0 * (r0.z + r4.z) + k1 * (r1.z + r2.z + r3.z);
            o.w = k0 * (r0.w + r4.w) + k1 * (r1.w + r2.w + r3.w);
            __half h0 = __float2half(o.x), h1 = __float2half(o.y);
            __half h2 = __float2half(o.z), h3 = __float2half(o.w);
            uint2 pk;
            pk.x = (uint32_t)__half_as_ushort(h0) | ((uint32_t)__half_as_ushort(h1) << 16);
            pk.y = (uint32_t)__half_as_ushort(h2) | ((uint32_t)__half_as_ushort(h3) << 16);
            dst[(size_t)zo * PP * 1568] = pk;
        }
    }
}

// ---------------- GEMM via mma.sync fp16 (HMMA.16816), single term ----------------
// CTA: 128 oc x 128 spatial. 8 warps: 2M x 4N, warp tile 64 x 32.
// 54 stages = 27 taps x 2 channel-halves (K=64). Stage = 2 tiles (W, X) x 16KB;
// 3 buffers = 96KB; cp.async depth-2 pipeline; 2 CTAs/SM.
__global__ __launch_bounds__(256, 2) void gemm_k(const float* __restrict__ bias,
                                                 float* __restrict__ out) {
    extern __shared__ char smem[];
    __shared__ int s_soff[128];
    uint32_t sb = smem_u32(smem);
    int tid = threadIdx.x, wid = tid >> 5, lane = tid & 31;
    int stile = blockIdx.x, ocg = blockIdx.y;
    int wm = (wid & 1) * 64;      // M (oc) offset in CTA tile
    int wn = (wid >> 1) * 32;     // N (spatial) offset

    // spatial base offsets (in 256B rows of channel-last layout) — computed once
    if (tid < 128) {
        int s = stile * 128 + tid;
        int n = s / 13824; int r = s % 13824;
        int oz = r / 576, r2 = r % 576, oy = r2 / 24, ox = r2 % 24;
        s_soff[tid] = ((n * 49 + 2 * oz) * 49 + 2 * oy) * 49 + 2 * ox;
    }
    __syncthreads();

    // issue cp.async for one stage (tap, half) into buffer b
    auto load_stage = [&](int st, int b) {
        int tap = st >> 1, half = st & 1;
        int dz = tap / 9, dy = (tap / 3) % 3, dx = tap % 3;
        int dtap = dz * 2401 + dy * 49 + dx;
        uint32_t bufbase = sb + b * 32768;
        size_t adelta = (size_t)tap * 65536 + half * 128;       // bytes into g_w
        size_t bdelta = (size_t)dtap * 256 + half * 128;        // bytes into g_xh
        #pragma unroll
        for (int it = 0; it < 8; it++) {
            int i = tid + it * 256;
            int t = i >> 10;            // 0=W 1=X
            int row = (i >> 3) & 127;
            int v = i & 7;
            const char* g;
            if (t == 0) {
                g = (const char*)g_w + adelta + (size_t)(ocg * 128 + row) * 256 + v * 16;
            } else {
                g = (const char*)g_xh + bdelta + (size_t)s_soff[row] * 256 + v * 16;
            }
            cp_async16(bufbase + t * 16384 + (uint32_t)(row * 128 + ((v ^ (row & 7)) * 16)), g);
        }
        cp_commit();
    };

    float acc[4][4][4];
    #pragma unroll
    for (int i = 0; i < 4; i++)
        #pragma unroll
        for (int j = 0; j < 4; j++)
            #pragma unroll
            for (int q = 0; q < 4; q++) acc[i][j][q] = 0.f;

    load_stage(0, 0);
    load_stage(1, 1);

    for (int st = 0; st < 54; st++) {
        int b = st % 3;
        if (st >= 52) asm volatile("cp.async.wait_group 0;" ::: "memory");
        else          asm volatile("cp.async.wait_group 1;" ::: "memory");
        __syncthreads();   // all warps done with stage st-1 -> safe to refill its buffer
        if (st + 2 < 54) load_stage(st + 2, (st + 2) % 3);

        uint32_t bufbase = sb + b * 32768;
        uint32_t tW = bufbase, tX = bufbase + 16384;

        #pragma unroll
        for (int ks = 0; ks < 4; ks++) {
            uint32_t aw[4][4];
            int arow = wm + (lane & 15);
            int akb = ks * 2 + (lane >> 4);
            #pragma unroll
            for (int i = 0; i < 4; i++)
                ldsm_x4(aw[i], sw_addr(tW, arow + i * 16, akb));
            int brow0 = wn + (lane & 7) + ((lane >> 4) << 3);
            int bkb = ks * 2 + ((lane >> 3) & 1);
            #pragma unroll
            for (int j2 = 0; j2 < 2; j2++) {
                uint32_t bh[4];
                ldsm_x4(bh, sw_addr(tX, brow0 + j2 * 16, bkb));
                #pragma unroll
                for (int i = 0; i < 4; i++) {
                    mma16816(acc[i][2 * j2],     aw[i], bh);      // n-lo
                    mma16816(acc[i][2 * j2 + 1], aw[i], bh + 2);  // n-hi
                }
            }
        }
    }

    // ---- epilogue: + bias, direct stores (pairs of consecutive spatial) ----
    #pragma unroll
    for (int i = 0; i < 4; i++) {
        int ocb = ocg * 128 + wm + i * 16 + (lane >> 2);
        float bv0 = bias[ocb], bv1 = bias[ocb + 8];
        #pragma unroll
        for (int j = 0; j < 4; j++) {
            int col = wn + j * 8 + (lane & 3) * 2;
            int s = stile * 128 + col;
            int nb = s / 13824, r2 = s % 13824;
            float2 v0 = make_float2(acc[i][j][0] + bv0, acc[i][j][1] + bv0);
            float2 v1 = make_float2(acc[i][j][2] + bv1, acc[i][j][3] + bv1);
            *(float2*)(out + ((size_t)(nb * OCN + ocb) * 13824 + r2)) = v0;
            *(float2*)(out + ((size_t)(nb * OCN + ocb + 8) * 13824 + r2)) = v1;
        }
    }
}

// ---------------- launch ----------------
extern "C" void kernel_launch(void* const* d_in, const int* in_sizes, int n_in,
                              void* d_out, int out_size) {
    const float* x    = (const float*)d_in[0];   // (2,128,48,48,48)
    const float* wgt  = (const float*)d_in[1];   // (256,128,3,3,3)
    const float* bias = (const float*)d_in[2];   // (256,)
    float* out = (float*)d_out;                  // (2,256,24,24,24)

    {
        int total = OCN * CC * 27;
        wprep<<<(total + 255) / 256, 256>>>(wgt);
    }
    {
        dim3 grid(48 * 48, NN);
        blurX<<<grid, 128>>>(x);
    }
    {
        int total = NN * PP * 1568;
        blurYZ<<<(total + 255) / 256, 256>>>();
    }
    {
        static int smem_set = 0;
        const int smem_bytes = 3 * 32768;   // 98304
        if (!smem_set) {
            cudaFuncSetAttribute(gemm_k, cudaFuncAttributeMaxDynamicSharedMemorySize, smem_bytes);
            smem_set = 1;
        }
        dim3 grid(STILES, 2);
        gemm_k<<<grid, 256, smem_bytes>>>(bias, out);
    }
}